// round 6
// baseline (speedup 1.0000x reference)
#include <cuda_runtime.h>
#include <math.h>

// Shapes (fixed by the problem)
#define BB 64      // batch
#define DD 512     // in dims
#define PP 128     // patches
#define NM 1152    // P*9 mask logits per batch
#define NT 768     // P*6 theta per batch
#define NO 1920    // NM + NT
#define SS 64      // scene size

// GEMM tiling
#define KSPLIT 16
#define KCH 32
#define OT 64
#define PAD 4

__device__ float g_part[KSPLIT][BB * NO];   // 7.86 MB k-split partials (L2-resident)

// ---------------------------------------------------------------------------
// Kernel A: partial GEMM (unchanged; ~5us)
// ---------------------------------------------------------------------------
__global__ __launch_bounds__(256) void gemm_part_kernel(
    const float* __restrict__ z, const float* __restrict__ Wm,
    const float* __restrict__ Wt)
{
    __shared__ float zs[BB][KCH + PAD];
    __shared__ float ws[OT][KCH + PAD];

    const int obase = blockIdx.x * OT;
    const int kbase = blockIdx.y * KCH;
    const int tid = threadIdx.x;

    for (int i = tid; i < BB * (KCH / 4); i += 256) {
        int b = i >> 3, k4 = i & 7;
        float4 v = *reinterpret_cast<const float4*>(z + b * DD + kbase + 4 * k4);
        *reinterpret_cast<float4*>(&zs[b][4 * k4]) = v;
    }
    for (int i = tid; i < OT * (KCH / 4); i += 256) {
        int o = i >> 3, k4 = i & 7;
        int og = obase + o;
        const float* row = (og < NM) ? (Wm + (size_t)og * DD)
                                     : (Wt + (size_t)(og - NM) * DD);
        float4 v = *reinterpret_cast<const float4*>(row + kbase + 4 * k4);
        *reinterpret_cast<float4*>(&ws[o][4 * k4]) = v;
    }
    __syncthreads();

    const int tx = tid & 15;
    const int ty = tid >> 4;

    float acc[4][4];
#pragma unroll
    for (int i = 0; i < 4; i++)
#pragma unroll
        for (int j = 0; j < 4; j++) acc[i][j] = 0.f;

#pragma unroll
    for (int k0 = 0; k0 < KCH; k0 += 4) {
        float4 wv[4], zv[4];
#pragma unroll
        for (int i = 0; i < 4; i++)
            wv[i] = *reinterpret_cast<const float4*>(&ws[tx + 16 * i][k0]);
#pragma unroll
        for (int j = 0; j < 4; j++)
            zv[j] = *reinterpret_cast<const float4*>(&zs[ty + 16 * j][k0]);
#pragma unroll
        for (int i = 0; i < 4; i++)
#pragma unroll
            for (int j = 0; j < 4; j++) {
                acc[i][j] = fmaf(wv[i].x, zv[j].x, acc[i][j]);
                acc[i][j] = fmaf(wv[i].y, zv[j].y, acc[i][j]);
                acc[i][j] = fmaf(wv[i].z, zv[j].z, acc[i][j]);
                acc[i][j] = fmaf(wv[i].w, zv[j].w, acc[i][j]);
            }
    }

    float* part = g_part[blockIdx.y];
#pragma unroll
    for (int j = 0; j < 4; j++) {
        int b = ty + 16 * j;
#pragma unroll
        for (int i = 0; i < 4; i++)
            part[b * NO + obase + tx + 16 * i] = acc[i][j];
    }
}

// Pack two floats into a 64-bit register pair (free when allocator co-locates).
__device__ __forceinline__ unsigned long long pack2(float x, float y)
{
    unsigned long long r;
    asm("mov.b64 %0, {%1, %2};" : "=l"(r) : "f"(x), "f"(y));
    return r;
}

// One bilinear tap: packed f32x2 coords -> magic-floor -> clamped LDS.128 LUT.
// a2={ax6,ay6} per-column terms, b2={bx6,by6} per-row terms (6-scaled table coords).
__device__ __forceinline__ float bilerp(
    unsigned long long a2, unsigned long long b2,
    unsigned long long magic2, unsigned long long nmagic2,
    unsigned long long neg1_2, unsigned qbase)
{
    float r;
    asm("{\n\t"
        ".reg .b64 c2, t2, f2, w2;\n\t"
        ".reg .f32 wx, wy, q0, q1, q2, q3, h0, wxy;\n\t"
        ".reg .b32 xi, yi, idx, adr;\n\t"
        "add.rn.f32x2 c2, %1, %2;\n\t"          // {ix, iy} unclamped
        "add.rz.f32x2 t2, c2, %3;\n\t"          // magic trunc: mantissa = floor
        "add.rn.f32x2 f2, t2, %4;\n\t"          // {fx, fy} exact
        "fma.rn.f32x2 w2, f2, %5, c2;\n\t"      // {wx, wy} = c2 - f2
        "mov.b64 {wx, wy}, w2;\n\t"
        "mov.b64 {xi, yi}, t2;\n\t"             // biased int bits
        "mad.lo.s32 idx, yi, 16, xi;\n\t"       // 16*fy + fx + 17*bias
        "add.s32 idx, idx, 12582912;\n\t"       // remove 17*0x4B400000 (mod 2^32)
        "min.u32 idx, idx, 127;\n\t"            // OOR -> zero cells
        "mad.lo.s32 adr, idx, 16, %6;\n\t"
        "ld.shared.v4.f32 {q0, q1, q2, q3}, [adr];\n\t"
        "mul.rn.f32 wxy, wx, wy;\n\t"
        "fma.rn.f32 h0, wx, q1, q0;\n\t"
        "fma.rn.f32 h0, wy, q2, h0;\n\t"
        "fma.rn.f32 %0, wxy, q3, h0;\n\t"
        "}"
        : "=f"(r)
        : "l"(a2), "l"(b2), "l"(magic2), "l"(nmagic2), "l"(neg1_2), "r"(qbase));
    return r;
}

// ---------------------------------------------------------------------------
// Kernel B: render. 8x16 zero-padded mask plane -> 128-cell float4 bilinear
// LUT. Table coords: ix = 1.5*gx + 3 (+2 pad offset), mask at rows/cols [2..4].
// Out-of-range indices alias into guaranteed-zero cells or the u32 clamp.
// ---------------------------------------------------------------------------
__global__ __launch_bounds__(256) void render_kernel(
    const float* __restrict__ bm, const float* __restrict__ bt,
    const float* __restrict__ noise, float* __restrict__ out)
{
    const int bp = blockIdx.x;          // b*128 + p
    const int b = bp >> 7, p = bp & 127;

    __shared__ float  smp[160];         // 9x16 zero plane (+pad); mask at [2..4][2..4]
    __shared__ float4 qtab[128];        // 8x16 bilinear cells
    __shared__ float  st[6];
    const int tid = threadIdx.x;

    if (tid < 160) smp[tid] = 0.f;

    float s = 0.f;
    if (tid >= 160 && tid < 175) {
        const int t = tid - 160;
        const int o = (t < 9) ? (p * 9 + t) : (NM + p * 6 + (t - 9));
        const float* gp = &g_part[0][b * NO + o];
#pragma unroll
        for (int kk = 0; kk < KSPLIT; kk++)
            s += gp[kk * (BB * NO)];
    }
    __syncthreads();
    if (tid >= 160 && tid < 175) {
        const int t = tid - 160;
        if (t < 9) {
            // 1 - sigmoid(x) == 1/(1+exp(x))
            float v = noise[t] / (1.f + expf(s + bm[p * 9 + t]));
            smp[((t / 3) + 2) * 16 + (t % 3) + 2] = v;
        } else {
            st[t - 9] = s + bt[p * 6 + (t - 9)];
        }
    }
    __syncthreads();
    if (tid < 128) {
        const float v00 = smp[tid];
        const float v01 = smp[tid + 1];
        const float v10 = smp[tid + 16];
        const float v11 = smp[tid + 17];
        qtab[tid] = make_float4(v00, v01 - v00, v10 - v00, v11 - v10 - v01 + v00);
    }
    __syncthreads();

    const float t00 = st[0], t01 = st[1], t02 = st[2];
    const float t10 = st[3], t11 = st[4], t12 = st[5];

    // table coord = 1.5*(theta . [cx,cy,1]) + 3
    const int xq = (tid & 15) << 2;     // this thread's 4 consecutive columns
    const int y0 = tid >> 4;            // base row; iterations add 16

    unsigned long long a2[4];
#pragma unroll
    for (int d = 0; d < 4; d++) {
        const float cx = (xq + d + 0.5f) * (1.f / 32.f) - 1.f;
        a2[d] = pack2(1.5f * t00 * cx, 1.5f * t10 * cx);
    }
    const float ct01 = 1.5f * t01, ct11 = 1.5f * t11;
    const float cx0  = fmaf(1.5f, t02, 3.f);
    const float cy0  = fmaf(1.5f, t12, 3.f);

    const unsigned long long MAGIC2  = 0x4B4000004B400000ULL;  // {1.5*2^23, same}
    const unsigned long long NMAGIC2 = 0xCB400000CB400000ULL;  // negated
    const unsigned long long NEG1_2  = 0xBF800000BF800000ULL;  // {-1,-1}

    const unsigned qbase = (unsigned)__cvta_generic_to_shared(qtab);
    float4* o4 = reinterpret_cast<float4*>(out + (size_t)bp * (SS * SS));

#pragma unroll
    for (int it = 0; it < 4; it++) {
        const int y = y0 + 16 * it;
        const float cy = (y + 0.5f) * (1.f / 32.f) - 1.f;
        const unsigned long long b2 =
            pack2(fmaf(ct01, cy, cx0), fmaf(ct11, cy, cy0));
        float4 r;
        r.x = bilerp(a2[0], b2, MAGIC2, NMAGIC2, NEG1_2, qbase);
        r.y = bilerp(a2[1], b2, MAGIC2, NMAGIC2, NEG1_2, qbase);
        r.z = bilerp(a2[2], b2, MAGIC2, NMAGIC2, NEG1_2, qbase);
        r.w = bilerp(a2[3], b2, MAGIC2, NMAGIC2, NEG1_2, qbase);
        __stcs(o4 + (y << 4) + (xq >> 2), r);
    }
}

extern "C" void kernel_launch(void* const* d_in, const int* in_sizes, int n_in,
                              void* d_out, int out_size)
{
    const float* z     = (const float*)d_in[0];
    const float* Wm    = (const float*)d_in[1];
    const float* bm    = (const float*)d_in[2];
    const float* Wt    = (const float*)d_in[3];
    const float* bt    = (const float*)d_in[4];
    const float* noise = (const float*)d_in[5];
    float* out = (float*)d_out;

    gemm_part_kernel<<<dim3(NO / OT, KSPLIT), 256>>>(z, Wm, Wt);
    render_kernel<<<BB * PP, 256>>>(bm, bt, noise, out);
}

// round 8
// speedup vs baseline: 1.0024x; 1.0024x over previous
#include <cuda_runtime.h>
#include <math.h>

// Shapes (fixed by the problem)
#define BB 64      // batch
#define DD 512     // in dims
#define PP 128     // patches
#define NM 1152    // P*9 mask logits per batch
#define NT 768     // P*6 theta per batch
#define NO 1920    // NM + NT
#define SS 64      // scene size

// GEMM tiling
#define KSPLIT 32
#define KCH 16
#define OT 64
#define PAD 4

__device__ float g_part[KSPLIT][BB * NO];   // k-split partials (L2-resident)

// ---------------------------------------------------------------------------
// Kernel A: partial GEMM. grid=(30,32)=960 blocks -> 6.5/SM, single wave.
// ---------------------------------------------------------------------------
__global__ __launch_bounds__(256) void gemm_part_kernel(
    const float* __restrict__ z, const float* __restrict__ Wm,
    const float* __restrict__ Wt)
{
    __shared__ float zs[BB][KCH + PAD];
    __shared__ float ws[OT][KCH + PAD];

    const int obase = blockIdx.x * OT;
    const int kbase = blockIdx.y * KCH;
    const int tid = threadIdx.x;

    for (int i = tid; i < BB * (KCH / 4); i += 256) {
        int b = i >> 2, k4 = i & 3;
        float4 v = *reinterpret_cast<const float4*>(z + b * DD + kbase + 4 * k4);
        *reinterpret_cast<float4*>(&zs[b][4 * k4]) = v;
    }
    for (int i = tid; i < OT * (KCH / 4); i += 256) {
        int o = i >> 2, k4 = i & 3;
        int og = obase + o;
        const float* row = (og < NM) ? (Wm + (size_t)og * DD)
                                     : (Wt + (size_t)(og - NM) * DD);
        float4 v = *reinterpret_cast<const float4*>(row + kbase + 4 * k4);
        *reinterpret_cast<float4*>(&ws[o][4 * k4]) = v;
    }
    __syncthreads();

    const int tx = tid & 15;
    const int ty = tid >> 4;

    float acc[4][4];
#pragma unroll
    for (int i = 0; i < 4; i++)
#pragma unroll
        for (int j = 0; j < 4; j++) acc[i][j] = 0.f;

#pragma unroll
    for (int k0 = 0; k0 < KCH; k0 += 4) {
        float4 wv[4], zv[4];
#pragma unroll
        for (int i = 0; i < 4; i++)
            wv[i] = *reinterpret_cast<const float4*>(&ws[tx + 16 * i][k0]);
#pragma unroll
        for (int j = 0; j < 4; j++)
            zv[j] = *reinterpret_cast<const float4*>(&zs[ty + 16 * j][k0]);
#pragma unroll
        for (int i = 0; i < 4; i++)
#pragma unroll
            for (int j = 0; j < 4; j++) {
                acc[i][j] = fmaf(wv[i].x, zv[j].x, acc[i][j]);
                acc[i][j] = fmaf(wv[i].y, zv[j].y, acc[i][j]);
                acc[i][j] = fmaf(wv[i].z, zv[j].z, acc[i][j]);
                acc[i][j] = fmaf(wv[i].w, zv[j].w, acc[i][j]);
            }
    }

    float* part = g_part[blockIdx.y];
#pragma unroll
    for (int j = 0; j < 4; j++) {
        int b = ty + 16 * j;
#pragma unroll
        for (int i = 0; i < 4; i++)
            part[b * NO + obase + tx + 16 * i] = acc[i][j];
    }
}

// ---------------------------------------------------------------------------
// Kernel B: render. 8x16 zero-padded mask plane -> 128-cell float4 bilinear
// LUT: qtab[a] = {v00, v01-v00, v10-v00, v11-v10-v01+v00}.
// Table coord ix6 = 1.5*gx + 3 (mask at rows/cols [2..4]). No saturate:
//   - x out of range wraps into cols {0,1,5..15} of same/adjacent row - all
//     zero cells (cols 0,1 and 5+ of every row are zero).
//   - fy in [0..7] with any in-range fx: rows 0,1,5,6,7 are all-zero cells.
//   - fy < 0 or huge: ab negative/large -> min.u32 clamp -> cell 127, whose
//     4 taps (smp[127],[128],[143],[144]) lie in the extended zero plane.
// smp is 176 floats (11 zero rows) so cell 127's taps are genuinely zero
// (R7 bug: smp[144] read past a 144-float array into theta).
// ---------------------------------------------------------------------------
__global__ __launch_bounds__(256) void render_kernel(
    const float* __restrict__ bm, const float* __restrict__ bt,
    const float* __restrict__ noise, float* __restrict__ out)
{
    const int bp = blockIdx.x;          // b*128 + p
    const int b = bp >> 7, p = bp & 127;

    __shared__ float  smp[176];         // 11x16 zero plane; mask at [2..4][2..4]
    __shared__ float4 qtab[128];        // 8x16 bilinear cells
    __shared__ float  st[6];
    const int tid = threadIdx.x;

    if (tid < 176) smp[tid] = 0.f;

    float s = 0.f;
    if (tid >= 192 && tid < 207) {
        const int t = tid - 192;
        const int o = (t < 9) ? (p * 9 + t) : (NM + p * 6 + (t - 9));
        const float* gp = &g_part[0][b * NO + o];
#pragma unroll
        for (int kk = 0; kk < KSPLIT; kk++)
            s += gp[kk * (BB * NO)];
    }
    __syncthreads();
    if (tid >= 192 && tid < 207) {
        const int t = tid - 192;
        if (t < 9) {
            // 1 - sigmoid(x) == 1/(1+exp(x))
            float v = noise[t] / (1.f + expf(s + bm[p * 9 + t]));
            smp[((t / 3) + 2) * 16 + (t % 3) + 2] = v;
        } else {
            st[t - 9] = s + bt[p * 6 + (t - 9)];
        }
    }
    __syncthreads();
    if (tid < 128) {
        const float v00 = smp[tid];
        const float v01 = smp[tid + 1];
        const float v10 = smp[tid + 16];
        const float v11 = smp[tid + 17];
        qtab[tid] = make_float4(v00, v01 - v00, v10 - v00, v11 - v10 - v01 + v00);
    }
    __syncthreads();

    const float t00 = st[0], t01 = st[1], t02 = st[2];
    const float t10 = st[3], t11 = st[4], t12 = st[5];

    // table coord = 1.5*(theta . [cx,cy,1]) + 3
    const int xq = (tid & 15) << 2;     // this thread's 4 consecutive columns
    const int y0 = tid >> 4;            // base row; iterations add 16

    float axd[4], ayd[4];
#pragma unroll
    for (int d = 0; d < 4; d++) {
        const float cx = (xq + d + 0.5f) * (1.f / 32.f) - 1.f;
        axd[d] = 1.5f * t00 * cx;
        ayd[d] = 1.5f * t10 * cx;
    }
    const float ct01 = 1.5f * t01, ct11 = 1.5f * t11;
    const float cx0  = fmaf(1.5f, t02, 3.f);
    const float cy0  = fmaf(1.5f, t12, 3.f);

    const char* qbase = reinterpret_cast<const char*>(qtab);
    float4* o4 = reinterpret_cast<float4*>(out + (size_t)bp * (SS * SS));

#pragma unroll
    for (int it = 0; it < 4; it++) {
        const int y = y0 + 16 * it;
        const float cy = (y + 0.5f) * (1.f / 32.f) - 1.f;
        const float bx = fmaf(ct01, cy, cx0);
        const float by = fmaf(ct11, cy, cy0);
        float4 r;
        float* rp = &r.x;
#pragma unroll
        for (int d = 0; d < 4; d++) {
            const float ix6 = axd[d] + bx;
            const float iy6 = ayd[d] + by;
            const float fx = floorf(ix6);
            const float fy = floorf(iy6);
            const float wx = ix6 - fx;
            const float wy = iy6 - fy;
            // byte offset = fy*256 + fx*16; OOR -> zero cells / clamp target
            const int ab = (int)fmaf(fy, 256.f, fx * 16.f);
            const unsigned ua = min((unsigned)ab, 2032u);   // cell 127 is zero
            const float4 q = *reinterpret_cast<const float4*>(qbase + ua);
            const float wxy = wx * wy;
            float v = fmaf(wx, q.y, q.x);
            v = fmaf(wy, q.z, v);
            rp[d] = fmaf(wxy, q.w, v);
        }
        __stcs(o4 + (y << 4) + (xq >> 2), r);
    }
}

extern "C" void kernel_launch(void* const* d_in, const int* in_sizes, int n_in,
                              void* d_out, int out_size)
{
    const float* z     = (const float*)d_in[0];
    const float* Wm    = (const float*)d_in[1];
    const float* bm    = (const float*)d_in[2];
    const float* Wt    = (const float*)d_in[3];
    const float* bt    = (const float*)d_in[4];
    const float* noise = (const float*)d_in[5];
    float* out = (float*)d_out;

    gemm_part_kernel<<<dim3(NO / OT, KSPLIT), 256>>>(z, Wm, Wt);
    render_kernel<<<BB * PP, 256>>>(bm, bt, noise, out);
}

// round 9
// speedup vs baseline: 1.0115x; 1.0090x over previous
#include <cuda_runtime.h>
#include <math.h>

// Shapes (fixed by the problem)
#define BB 64      // batch
#define DD 512     // in dims
#define PP 128     // patches
#define NM 1152    // P*9 mask logits per batch
#define NT 768     // P*6 theta per batch
#define NO 1920    // NM + NT
#define SS 64      // scene size

// GEMM tiling (R8 config: 960 blocks, single wave, 6.5 blocks/SM)
#define KSPLIT 32
#define KCH 16
#define OT 64
#define PAD 4

__device__ float g_part[KSPLIT][BB * NO];   // k-split partials (L2-resident)

// ---------------------------------------------------------------------------
// Kernel A: partial GEMM. grid=(30,32)=960 blocks.
// ---------------------------------------------------------------------------
__global__ __launch_bounds__(256) void gemm_part_kernel(
    const float* __restrict__ z, const float* __restrict__ Wm,
    const float* __restrict__ Wt)
{
    __shared__ float zs[BB][KCH + PAD];
    __shared__ float ws[OT][KCH + PAD];

    const int obase = blockIdx.x * OT;
    const int kbase = blockIdx.y * KCH;
    const int tid = threadIdx.x;

    for (int i = tid; i < BB * (KCH / 4); i += 256) {
        int b = i >> 2, k4 = i & 3;
        float4 v = *reinterpret_cast<const float4*>(z + b * DD + kbase + 4 * k4);
        *reinterpret_cast<float4*>(&zs[b][4 * k4]) = v;
    }
    for (int i = tid; i < OT * (KCH / 4); i += 256) {
        int o = i >> 2, k4 = i & 3;
        int og = obase + o;
        const float* row = (og < NM) ? (Wm + (size_t)og * DD)
                                     : (Wt + (size_t)(og - NM) * DD);
        float4 v = *reinterpret_cast<const float4*>(row + kbase + 4 * k4);
        *reinterpret_cast<float4*>(&ws[o][4 * k4]) = v;
    }
    __syncthreads();

    const int tx = tid & 15;
    const int ty = tid >> 4;

    float acc[4][4];
#pragma unroll
    for (int i = 0; i < 4; i++)
#pragma unroll
        for (int j = 0; j < 4; j++) acc[i][j] = 0.f;

#pragma unroll
    for (int k0 = 0; k0 < KCH; k0 += 4) {
        float4 wv[4], zv[4];
#pragma unroll
        for (int i = 0; i < 4; i++)
            wv[i] = *reinterpret_cast<const float4*>(&ws[tx + 16 * i][k0]);
#pragma unroll
        for (int j = 0; j < 4; j++)
            zv[j] = *reinterpret_cast<const float4*>(&zs[ty + 16 * j][k0]);
#pragma unroll
        for (int i = 0; i < 4; i++)
#pragma unroll
            for (int j = 0; j < 4; j++) {
                acc[i][j] = fmaf(wv[i].x, zv[j].x, acc[i][j]);
                acc[i][j] = fmaf(wv[i].y, zv[j].y, acc[i][j]);
                acc[i][j] = fmaf(wv[i].z, zv[j].z, acc[i][j]);
                acc[i][j] = fmaf(wv[i].w, zv[j].w, acc[i][j]);
            }
    }

    float* part = g_part[blockIdx.y];
#pragma unroll
    for (int j = 0; j < 4; j++) {
        int b = ty + 16 * j;
#pragma unroll
        for (int i = 0; i < 4; i++)
            part[b * NO + obase + tx + 16 * i] = acc[i][j];
    }
}

// ---------------------------------------------------------------------------
// Kernel B: render (R5 structure — fastest measured variant).
// Zero-padded 8x8 mask folded into a 64-cell float4 bilinear LUT:
//   qtab[a] = {v00, v01-v00, v10-v00, v11-v10-v01+v00}
//   out = q.x + wx*q.y + wy*q.z + wx*wy*q.w  (1 LDS.128 + 1 FMUL + 3 FFMA)
// Saturate clamps coords into [0,1]; pad ring absorbs edge taps.
// ---------------------------------------------------------------------------
__global__ __launch_bounds__(256) void render_kernel(
    const float* __restrict__ bm, const float* __restrict__ bt,
    const float* __restrict__ noise, float* __restrict__ out)
{
    const int bp = blockIdx.x;          // b*128 + p
    const int b = bp >> 7, p = bp & 127;

    __shared__ float  smp[72];          // 8x8 zero-padded (+8 guard row)
    __shared__ float4 qtab[64];
    __shared__ float  st[6];
    const int tid = threadIdx.x;

    if (tid < 72) smp[tid] = 0.f;

    float s = 0.f;
    if (tid >= 128 && tid < 143) {
        const int t = tid - 128;
        const int o = (t < 9) ? (p * 9 + t) : (NM + p * 6 + (t - 9));
        const float* gp = &g_part[0][b * NO + o];
#pragma unroll
        for (int kk = 0; kk < KSPLIT; kk++)
            s += gp[kk * (BB * NO)];
    }
    __syncthreads();
    if (tid >= 128 && tid < 143) {
        const int t = tid - 128;
        if (t < 9) {
            // 1 - sigmoid(x) == 1/(1+exp(x))
            float v = noise[t] / (1.f + expf(s + bm[p * 9 + t]));
            smp[((t / 3) + 2) * 8 + (t % 3) + 2] = v;
        } else {
            st[t - 9] = s + bt[p * 6 + (t - 9)];
        }
    }
    __syncthreads();
    if (tid < 64) {
        // guard row (indices 64..71) is zero, so tid up to 63 is safe
        const float v00 = smp[tid];
        const float v01 = smp[tid + 1];
        const float v10 = smp[tid + 8];
        const float v11 = smp[tid + 9];
        qtab[tid] = make_float4(v00, v01 - v00, v10 - v00, v11 - v10 - v01 + v00);
    }
    __syncthreads();

    const float t00 = st[0], t01 = st[1], t02 = st[2];
    const float t10 = st[3], t11 = st[4], t12 = st[5];

    // u = 0.25*(theta . [cx,cy,1]) + 0.5 in [0,1]; sample coord = 6*sat(u).
    const int xq = (tid & 15) << 2;     // this thread's 4 consecutive columns
    const int y0 = tid >> 4;            // base row; iterations add 16

    float axd[4], ayd[4];
#pragma unroll
    for (int d = 0; d < 4; d++) {
        const float cx = (xq + d + 0.5f) * (1.f / 32.f) - 1.f;
        axd[d] = 0.25f * t00 * cx;
        ayd[d] = 0.25f * t10 * cx;
    }
    const float qt01 = 0.25f * t01, qt11 = 0.25f * t11;
    const float cx0  = fmaf(0.25f, t02, 0.5f);
    const float cy0  = fmaf(0.25f, t12, 0.5f);

    const char* qbase = reinterpret_cast<const char*>(qtab);
    float4* o4 = reinterpret_cast<float4*>(out + (size_t)bp * (SS * SS));

#pragma unroll
    for (int it = 0; it < 4; it++) {
        const int y = y0 + 16 * it;
        const float cy = (y + 0.5f) * (1.f / 32.f) - 1.f;
        const float bx = fmaf(qt01, cy, cx0);
        const float by = fmaf(qt11, cy, cy0);
        float4 r;
        float* rp = &r.x;
#pragma unroll
        for (int d = 0; d < 4; d++) {
            const float ux = __saturatef(axd[d] + bx);
            const float uy = __saturatef(ayd[d] + by);
            const float ix = ux * 6.f;            // in [0,6]; pad absorbs edges
            const float iy = uy * 6.f;
            const float fx = floorf(ix);
            const float fy = floorf(iy);
            const float wx = ix - fx;
            const float wy = iy - fy;
            // byte offset = (fy*8 + fx) * 16, exact small-int float math
            const int ab = (int)fmaf(fy, 128.f, fx * 16.f);   // <= 54*16, 16B aligned
            const float4 q = *reinterpret_cast<const float4*>(qbase + ab);
            const float wxy = wx * wy;
            float v = fmaf(wx, q.y, q.x);
            v = fmaf(wy, q.z, v);
            rp[d] = fmaf(wxy, q.w, v);
        }
        __stcs(o4 + (y << 4) + (xq >> 2), r);
    }
}

extern "C" void kernel_launch(void* const* d_in, const int* in_sizes, int n_in,
                              void* d_out, int out_size)
{
    const float* z     = (const float*)d_in[0];
    const float* Wm    = (const float*)d_in[1];
    const float* bm    = (const float*)d_in[2];
    const float* Wt    = (const float*)d_in[3];
    const float* bt    = (const float*)d_in[4];
    const float* noise = (const float*)d_in[5];
    float* out = (float*)d_out;

    gemm_part_kernel<<<dim3(NO / OT, KSPLIT), 256>>>(z, Wm, Wt);
    render_kernel<<<BB * PP, 256>>>(bm, bt, noise, out);
}